// round 1
// baseline (speedup 1.0000x reference)
#include <cuda_runtime.h>
#include <cuda_bf16.h>
#include <stdint.h>

// ---------------- problem constants ----------------
#define N_USERS 100000
#define N_ITEMS 50000
#define NNODES  150000           // N_USERS + N_ITEMS
#define EMB_DIM 64
#define NNZ     6400000
#define BATCH   4096
#define N_LAYERS 3

// ---------------- device scratch (static, allocation-free) ----------------
__device__ int   g_rowptr[NNODES + 1];     // CSR row pointers (by src)
__device__ int   g_fill[NNODES];           // scatter cursors
__device__ int   g_sorted_dst[NNZ];
__device__ float g_sorted_val[NNZ];
__device__ float g_x[2][NNODES * EMB_DIM]; // ping-pong layer buffers
__device__ float g_acc[NNODES * EMB_DIM];  // running sum of layers

// ---------------- build CSR: counting sort by src ----------------
__global__ void k_zero_counts() {
    int i = blockIdx.x * blockDim.x + threadIdx.x;
    if (i <= NNODES) g_rowptr[i] = 0;
}

__global__ void k_hist(const int* __restrict__ src) {
    int e = blockIdx.x * blockDim.x + threadIdx.x;
    if (e < NNZ) atomicAdd(&g_rowptr[src[e] + 1], 1);
}

// single-block inclusive scan over g_rowptr[0..NNODES]
__global__ void k_scan() {
    __shared__ int warp_sums[32];
    __shared__ int s_carry;
    const int lane = threadIdx.x & 31;
    const int wid  = threadIdx.x >> 5;
    if (threadIdx.x == 0) s_carry = 0;
    __syncthreads();

    for (int base = 0; base < NNODES + 1; base += 1024) {
        int i = base + (int)threadIdx.x;
        int v = (i < NNODES + 1) ? g_rowptr[i] : 0;

        // warp inclusive scan
        int x = v;
#pragma unroll
        for (int off = 1; off < 32; off <<= 1) {
            int t = __shfl_up_sync(0xffffffffu, x, off);
            if (lane >= off) x += t;
        }
        if (lane == 31) warp_sums[wid] = x;
        __syncthreads();
        if (wid == 0) {
            int w = warp_sums[lane];
#pragma unroll
            for (int off = 1; off < 32; off <<= 1) {
                int t = __shfl_up_sync(0xffffffffu, w, off);
                if (lane >= off) w += t;
            }
            warp_sums[lane] = w;
        }
        __syncthreads();
        int warp_off = (wid > 0) ? warp_sums[wid - 1] : 0;
        int incl = x + warp_off + s_carry;
        if (i < NNODES + 1) g_rowptr[i] = incl;
        int chunk_total = warp_sums[31];
        __syncthreads();
        if (threadIdx.x == 0) s_carry += chunk_total;
        __syncthreads();
    }
}

__global__ void k_copy_fill() {
    int i = blockIdx.x * blockDim.x + threadIdx.x;
    if (i < NNODES) g_fill[i] = g_rowptr[i];
}

__global__ void k_scatter(const int* __restrict__ src,
                          const int* __restrict__ dst,
                          const float* __restrict__ val) {
    int e = blockIdx.x * blockDim.x + threadIdx.x;
    if (e < NNZ) {
        int s = src[e];
        int pos = atomicAdd(&g_fill[s], 1);
        g_sorted_dst[pos] = dst[e];
        g_sorted_val[pos] = val[e];
    }
}

// ---------------- init x0 = concat(user_emb, item_emb); acc = x0 ----------------
__global__ void k_init_x(const float* __restrict__ user_emb,
                         const float* __restrict__ item_emb) {
    int i = blockIdx.x * blockDim.x + threadIdx.x;
    const int total = NNODES * EMB_DIM;
    if (i < total) {
        float v = (i < N_USERS * EMB_DIM) ? user_emb[i]
                                          : item_emb[i - N_USERS * EMB_DIM];
        g_x[0][i] = v;
        g_acc[i]  = v;
    }
}

// ---------------- SpMM: one warp per row, pull-based CSR ----------------
// out[row, :] = sum_e val[e] * x[dst[e], :];  acc[row, :] += out[row, :]
__global__ void __launch_bounds__(256) k_spmm(int cur) {
    const int warp_global = (blockIdx.x * blockDim.x + threadIdx.x) >> 5;
    const int lane = threadIdx.x & 31;
    if (warp_global >= NNODES) return;
    const int row = warp_global;

    const float2* __restrict__ X = (const float2*)&g_x[cur][0];
    float2* __restrict__ Xout    = (float2*)&g_x[cur ^ 1][0];
    float2* __restrict__ A       = (float2*)&g_acc[0];

    int beg = g_rowptr[row];
    int end = g_rowptr[row + 1];

    float sx = 0.f, sy = 0.f;

    int e = beg;
    // full 32-edge chunks: coalesced edge loads + shfl broadcast
    for (; e + 32 <= end; e += 32) {
        int   d = g_sorted_dst[e + lane];
        float v = g_sorted_val[e + lane];
#pragma unroll 8
        for (int j = 0; j < 32; j++) {
            int   dj = __shfl_sync(0xffffffffu, d, j);
            float vj = __shfl_sync(0xffffffffu, v, j);
            float2 xv = __ldg(&X[dj * 32 + lane]);
            sx = fmaf(vj, xv.x, sx);
            sy = fmaf(vj, xv.y, sy);
        }
    }
    // tail
    int rem = end - e;
    if (rem > 0) {
        int   d = 0; float v = 0.f;
        if (lane < rem) {
            d = g_sorted_dst[e + lane];
            v = g_sorted_val[e + lane];
        }
        for (int j = 0; j < rem; j++) {
            int   dj = __shfl_sync(0xffffffffu, d, j);
            float vj = __shfl_sync(0xffffffffu, v, j);
            float2 xv = __ldg(&X[dj * 32 + lane]);
            sx = fmaf(vj, xv.x, sx);
            sy = fmaf(vj, xv.y, sy);
        }
    }

    float2 out; out.x = sx; out.y = sy;
    Xout[row * 32 + lane] = out;
    float2 a = A[row * 32 + lane];
    a.x += sx; a.y += sy;
    A[row * 32 + lane] = a;
}

// ---------------- final scores: one warp per pair ----------------
// light_out = acc/4; score = dot(acc_u, acc_i) / 16
__global__ void k_score(const int* __restrict__ users,
                        const int* __restrict__ items,
                        float* __restrict__ out) {
    const int warp_global = (blockIdx.x * blockDim.x + threadIdx.x) >> 5;
    const int lane = threadIdx.x & 31;
    if (warp_global >= BATCH) return;

    int u  = users[warp_global];
    int it = items[warp_global];

    const float2* __restrict__ A = (const float2*)&g_acc[0];
    float2 a = A[u * 32 + lane];
    float2 c = A[(N_USERS + it) * 32 + lane];
    float s = a.x * c.x + a.y * c.y;
#pragma unroll
    for (int off = 16; off > 0; off >>= 1)
        s += __shfl_xor_sync(0xffffffffu, s, off);
    if (lane == 0) out[warp_global] = s * (1.0f / 16.0f);
}

// ---------------- launch ----------------
extern "C" void kernel_launch(void* const* d_in, const int* in_sizes, int n_in,
                              void* d_out, int out_size) {
    const float* user_emb = (const float*)d_in[0];
    const float* item_emb = (const float*)d_in[1];
    const float* graph_val = (const float*)d_in[2];
    const int*   graph_src = (const int*)d_in[3];
    const int*   graph_dst = (const int*)d_in[4];
    const int*   users     = (const int*)d_in[5];
    const int*   items     = (const int*)d_in[6];
    float* out = (float*)d_out;

    // CSR build (reused by all 3 layers)
    k_zero_counts<<<(NNODES + 1 + 255) / 256, 256>>>();
    k_hist<<<(NNZ + 255) / 256, 256>>>(graph_src);
    k_scan<<<1, 1024>>>();
    k_copy_fill<<<(NNODES + 255) / 256, 256>>>();
    k_scatter<<<(NNZ + 255) / 256, 256>>>(graph_src, graph_dst, graph_val);

    // x0 / acc init
    k_init_x<<<(NNODES * EMB_DIM + 255) / 256, 256>>>(user_emb, item_emb);

    // 3 propagation layers (warp per row, 8 warps/block)
    const int spmm_blocks = (NNODES + 7) / 8;
    int cur = 0;
    for (int l = 0; l < N_LAYERS; l++) {
        k_spmm<<<spmm_blocks, 256>>>(cur);
        cur ^= 1;
    }

    // scores
    k_score<<<(BATCH + 7) / 8, 256>>>(users, items, out);
}

// round 2
// speedup vs baseline: 1.1264x; 1.1264x over previous
#include <cuda_runtime.h>
#include <cuda_fp16.h>
#include <stdint.h>

// ---------------- problem constants ----------------
#define N_USERS 100000
#define N_ITEMS 50000
#define NNODES  150000           // N_USERS + N_ITEMS
#define EMB_DIM 64
#define NNZ     6400000
#define BATCH   4096
#define N_LAYERS 3

// ---------------- device scratch (static, allocation-free) ----------------
__device__ int    g_rowptr[NNODES + 1];   // CSR row pointers (by src)
__device__ int    g_fill[NNODES];         // scatter cursors
__device__ int2   g_edges[NNZ];           // packed {dst, val_bits}, sorted by src
__device__ __half g_xh[N_LAYERS + 1][NNODES * EMB_DIM]; // x0..x3 in fp16

// ---------------- build CSR: counting sort by src ----------------
__global__ void k_zero_counts() {
    int i = blockIdx.x * blockDim.x + threadIdx.x;
    if (i <= NNODES) g_rowptr[i] = 0;
}

__global__ void k_hist(const int4* __restrict__ src4) {
    int t = blockIdx.x * blockDim.x + threadIdx.x;
    if (t < NNZ / 4) {
        int4 s = src4[t];
        atomicAdd(&g_rowptr[s.x + 1], 1);
        atomicAdd(&g_rowptr[s.y + 1], 1);
        atomicAdd(&g_rowptr[s.z + 1], 1);
        atomicAdd(&g_rowptr[s.w + 1], 1);
    }
}

// single-block inclusive scan over g_rowptr[0..NNODES]; also seeds g_fill
__global__ void k_scan() {
    __shared__ int warp_sums[32];
    __shared__ int s_carry;
    const int lane = threadIdx.x & 31;
    const int wid  = threadIdx.x >> 5;
    if (threadIdx.x == 0) s_carry = 0;
    __syncthreads();

    for (int base = 0; base < NNODES + 1; base += 1024) {
        int i = base + (int)threadIdx.x;
        int v = (i < NNODES + 1) ? g_rowptr[i] : 0;

        int x = v;
#pragma unroll
        for (int off = 1; off < 32; off <<= 1) {
            int t = __shfl_up_sync(0xffffffffu, x, off);
            if (lane >= off) x += t;
        }
        if (lane == 31) warp_sums[wid] = x;
        __syncthreads();
        if (wid == 0) {
            int w = warp_sums[lane];
#pragma unroll
            for (int off = 1; off < 32; off <<= 1) {
                int t = __shfl_up_sync(0xffffffffu, w, off);
                if (lane >= off) w += t;
            }
            warp_sums[lane] = w;
        }
        __syncthreads();
        int warp_off = (wid > 0) ? warp_sums[wid - 1] : 0;
        int incl = x + warp_off + s_carry;
        if (i < NNODES + 1) {
            g_rowptr[i] = incl;
            if (i < NNODES) g_fill[i] = incl;
        }
        int chunk_total = warp_sums[31];
        __syncthreads();
        if (threadIdx.x == 0) s_carry += chunk_total;
        __syncthreads();
    }
}

__global__ void k_scatter(const int4* __restrict__ src4,
                          const int4* __restrict__ dst4,
                          const float4* __restrict__ val4) {
    int t = blockIdx.x * blockDim.x + threadIdx.x;
    if (t < NNZ / 4) {
        int4   s = src4[t];
        int4   d = dst4[t];
        float4 v = val4[t];
        int p;
        p = atomicAdd(&g_fill[s.x], 1); g_edges[p] = make_int2(d.x, __float_as_int(v.x));
        p = atomicAdd(&g_fill[s.y], 1); g_edges[p] = make_int2(d.y, __float_as_int(v.y));
        p = atomicAdd(&g_fill[s.z], 1); g_edges[p] = make_int2(d.z, __float_as_int(v.z));
        p = atomicAdd(&g_fill[s.w], 1); g_edges[p] = make_int2(d.w, __float_as_int(v.w));
    }
}

// ---------------- init: x0 = fp16(concat(user_emb, item_emb)) ----------------
__global__ void k_init_x(const float2* __restrict__ user_emb,
                         const float2* __restrict__ item_emb) {
    int i = blockIdx.x * blockDim.x + threadIdx.x;    // index in float2 units
    const int total = NNODES * EMB_DIM / 2;
    if (i < total) {
        const int usplit = N_USERS * EMB_DIM / 2;
        float2 v = (i < usplit) ? user_emb[i] : item_emb[i - usplit];
        ((__half2*)&g_xh[0][0])[i] = __floats2half2_rn(v.x, v.y);
    }
}

// ---------------- SpMM: one warp per row, pull-based CSR, fp16 features ----
__global__ void __launch_bounds__(256) k_spmm(int layer) {
    const int row  = (blockIdx.x * blockDim.x + threadIdx.x) >> 5;
    const int lane = threadIdx.x & 31;
    if (row >= NNODES) return;

    const __half2* __restrict__ X = (const __half2*)&g_xh[layer - 1][0];
    __half2* __restrict__ Xout    = (__half2*)&g_xh[layer][0];

    int beg = g_rowptr[row];
    int end = g_rowptr[row + 1];

    float sx = 0.f, sy = 0.f;

    int e = beg;
    for (; e + 32 <= end; e += 32) {
        int2 ev = g_edges[e + lane];
#pragma unroll 8
        for (int j = 0; j < 32; j++) {
            int   dj = __shfl_sync(0xffffffffu, ev.x, j);
            float vj = __int_as_float(__shfl_sync(0xffffffffu, ev.y, j));
            float2 xv = __half22float2(__ldg(&X[dj * 32 + lane]));
            sx = fmaf(vj, xv.x, sx);
            sy = fmaf(vj, xv.y, sy);
        }
    }
    int rem = end - e;
    if (rem > 0) {
        int2 ev = make_int2(0, 0);
        if (lane < rem) ev = g_edges[e + lane];
        for (int j = 0; j < rem; j++) {
            int   dj = __shfl_sync(0xffffffffu, ev.x, j);
            float vj = __int_as_float(__shfl_sync(0xffffffffu, ev.y, j));
            float2 xv = __half22float2(__ldg(&X[dj * 32 + lane]));
            sx = fmaf(vj, xv.x, sx);
            sy = fmaf(vj, xv.y, sy);
        }
    }

    Xout[row * 32 + lane] = __floats2half2_rn(sx, sy);
}

// ---------------- final scores: one warp per pair ----------------
// acc = x0 + x1 + x2 + x3 (x0 in fp32 straight from inputs); score = dot/16
__global__ void k_score(const int* __restrict__ users,
                        const int* __restrict__ items,
                        const float2* __restrict__ user_emb,
                        const float2* __restrict__ item_emb,
                        float* __restrict__ out) {
    const int pair = (blockIdx.x * blockDim.x + threadIdx.x) >> 5;
    const int lane = threadIdx.x & 31;
    if (pair >= BATCH) return;

    int u  = users[pair];
    int it = items[pair];
    int urow = u;
    int irow = N_USERS + it;

    float2 au = user_emb[u * 32 + lane];
    float2 ai = item_emb[it * 32 + lane];
#pragma unroll
    for (int l = 1; l <= N_LAYERS; l++) {
        const __half2* __restrict__ X = (const __half2*)&g_xh[l][0];
        float2 xu = __half22float2(X[urow * 32 + lane]);
        float2 xi = __half22float2(X[irow * 32 + lane]);
        au.x += xu.x; au.y += xu.y;
        ai.x += xi.x; ai.y += xi.y;
    }

    float s = au.x * ai.x + au.y * ai.y;
#pragma unroll
    for (int off = 16; off > 0; off >>= 1)
        s += __shfl_xor_sync(0xffffffffu, s, off);
    if (lane == 0) out[pair] = s * (1.0f / 16.0f);
}

// ---------------- launch ----------------
extern "C" void kernel_launch(void* const* d_in, const int* in_sizes, int n_in,
                              void* d_out, int out_size) {
    const float* user_emb  = (const float*)d_in[0];
    const float* item_emb  = (const float*)d_in[1];
    const float* graph_val = (const float*)d_in[2];
    const int*   graph_src = (const int*)d_in[3];
    const int*   graph_dst = (const int*)d_in[4];
    const int*   users     = (const int*)d_in[5];
    const int*   items     = (const int*)d_in[6];
    float* out = (float*)d_out;

    // CSR build (reused by all 3 layers)
    k_zero_counts<<<(NNODES + 1 + 255) / 256, 256>>>();
    k_hist<<<(NNZ / 4 + 255) / 256, 256>>>((const int4*)graph_src);
    k_scan<<<1, 1024>>>();
    k_scatter<<<(NNZ / 4 + 255) / 256, 256>>>((const int4*)graph_src,
                                              (const int4*)graph_dst,
                                              (const float4*)graph_val);

    // x0 -> fp16
    k_init_x<<<(NNODES * EMB_DIM / 2 + 255) / 256, 256>>>(
        (const float2*)user_emb, (const float2*)item_emb);

    // 3 propagation layers (warp per row, 8 warps/block)
    const int spmm_blocks = (NNODES + 7) / 8;
    for (int l = 1; l <= N_LAYERS; l++)
        k_spmm<<<spmm_blocks, 256>>>(l);

    // scores
    k_score<<<(BATCH + 7) / 8, 256>>>(users, items,
                                      (const float2*)user_emb,
                                      (const float2*)item_emb, out);
}

// round 3
// speedup vs baseline: 1.1487x; 1.0198x over previous
#include <cuda_runtime.h>
#include <cuda_fp16.h>
#include <stdint.h>

// ---------------- problem constants ----------------
#define N_USERS 100000
#define N_ITEMS 50000
#define NNODES  150000           // N_USERS + N_ITEMS
#define EMB_DIM 64
#define NNZ     6400000
#define BATCH   4096
#define N_LAYERS 3
#define NPART   ((NNODES + 1 + 1023) / 1024)   // 147 scan partials

// val in [0, 0.05): 14-bit fixed point.  q = rn(val * 327680), v = q / 327680
#define VAL_SCALE   327680.0f
#define VAL_INV     (1.0f / 327680.0f)

// ---------------- device scratch (static, allocation-free) ----------------
__device__ int            g_rowptr[NNODES + 1];  // CSR row pointers (by src)
__device__ int            g_part[256];           // scan partials
__device__ unsigned short g_rank[NNZ];           // per-edge rank within its src row
__device__ unsigned int   g_edges[NNZ];          // packed (dst<<14 | q14(val)), sorted by src
__device__ __half         g_xh[N_LAYERS + 1][NNODES * EMB_DIM]; // x0..x3 fp16

// ---------------- CSR build: counting sort by src -------------------------
__global__ void k_zero_counts() {
    int i = blockIdx.x * blockDim.x + threadIdx.x;
    if (i <= NNODES) g_rowptr[i] = 0;
}

// histogram + per-edge rank (atomicAdd's return value IS the rank)
__global__ void k_hist(const int4* __restrict__ src4) {
    int t = blockIdx.x * blockDim.x + threadIdx.x;
    if (t < NNZ / 4) {
        int4 s = src4[t];
        ushort4 r;
        r.x = (unsigned short)atomicAdd(&g_rowptr[s.x + 1], 1);
        r.y = (unsigned short)atomicAdd(&g_rowptr[s.y + 1], 1);
        r.z = (unsigned short)atomicAdd(&g_rowptr[s.z + 1], 1);
        r.w = (unsigned short)atomicAdd(&g_rowptr[s.w + 1], 1);
        ((ushort4*)g_rank)[t] = r;
    }
}

// hierarchical inclusive scan over g_rowptr[0..NNODES]
__global__ void k_scan1() {
    __shared__ int warp_sums[32];
    const int lane = threadIdx.x & 31;
    const int wid  = threadIdx.x >> 5;
    int idx = blockIdx.x * 1024 + threadIdx.x;
    int v = (idx <= NNODES) ? g_rowptr[idx] : 0;

    int x = v;
#pragma unroll
    for (int off = 1; off < 32; off <<= 1) {
        int t = __shfl_up_sync(0xffffffffu, x, off);
        if (lane >= off) x += t;
    }
    if (lane == 31) warp_sums[wid] = x;
    __syncthreads();
    if (wid == 0) {
        int w = warp_sums[lane];
#pragma unroll
        for (int off = 1; off < 32; off <<= 1) {
            int t = __shfl_up_sync(0xffffffffu, w, off);
            if (lane >= off) w += t;
        }
        warp_sums[lane] = w;
    }
    __syncthreads();
    int incl = x + ((wid > 0) ? warp_sums[wid - 1] : 0);
    if (idx <= NNODES) g_rowptr[idx] = incl;
    if (threadIdx.x == 1023) g_part[blockIdx.x] = incl;
}

__global__ void k_scan2() {   // single block of 256, scans NPART partials
    __shared__ int s[256];
    int t = threadIdx.x;
    s[t] = (t < NPART) ? g_part[t] : 0;
    __syncthreads();
#pragma unroll
    for (int off = 1; off < 256; off <<= 1) {
        int v = (t >= off) ? s[t - off] : 0;
        __syncthreads();
        s[t] += v;
        __syncthreads();
    }
    if (t < NPART) g_part[t] = s[t];
}

__global__ void k_scan3() {   // add block offsets (blocks 1..NPART-1)
    int b = blockIdx.x + 1;
    int idx = b * 1024 + threadIdx.x;
    if (idx <= NNODES) g_rowptr[idx] += g_part[b - 1];
}

__device__ __forceinline__ unsigned int pack_edge(int d, float v) {
    unsigned int q = __float2uint_rn(v * VAL_SCALE);
    if (q > 16383u) q = 16383u;
    return ((unsigned int)d << 14) | q;
}

// atomic-free scatter: pos = rowptr[src] + rank
__global__ void k_scatter(const int4* __restrict__ src4,
                          const int4* __restrict__ dst4,
                          const float4* __restrict__ val4) {
    int t = blockIdx.x * blockDim.x + threadIdx.x;
    if (t < NNZ / 4) {
        int4    s = src4[t];
        int4    d = dst4[t];
        float4  v = val4[t];
        ushort4 r = ((const ushort4*)g_rank)[t];
        int p0 = g_rowptr[s.x] + r.x;
        int p1 = g_rowptr[s.y] + r.y;
        int p2 = g_rowptr[s.z] + r.z;
        int p3 = g_rowptr[s.w] + r.w;
        g_edges[p0] = pack_edge(d.x, v.x);
        g_edges[p1] = pack_edge(d.y, v.y);
        g_edges[p2] = pack_edge(d.z, v.z);
        g_edges[p3] = pack_edge(d.w, v.w);
    }
}

// ---------------- init: x0 = fp16(concat(user_emb, item_emb)) --------------
__global__ void k_init_x(const float2* __restrict__ user_emb,
                         const float2* __restrict__ item_emb) {
    int i = blockIdx.x * blockDim.x + threadIdx.x;    // float2 units
    const int total = NNODES * EMB_DIM / 2;
    if (i < total) {
        const int usplit = N_USERS * EMB_DIM / 2;
        float2 v = (i < usplit) ? user_emb[i] : item_emb[i - usplit];
        ((__half2*)&g_xh[0][0])[i] = __floats2half2_rn(v.x, v.y);
    }
}

// ---------------- SpMM: warp per row, packed edges, fp16 features ----------
__global__ void __launch_bounds__(256) k_spmm(int layer) {
    const int row  = (blockIdx.x * blockDim.x + threadIdx.x) >> 5;
    const int lane = threadIdx.x & 31;
    if (row >= NNODES) return;

    const __half2* __restrict__ X = (const __half2*)&g_xh[layer - 1][0];
    __half2* __restrict__ Xout    = (__half2*)&g_xh[layer][0];

    int beg = g_rowptr[row];
    int end = g_rowptr[row + 1];

    float sx = 0.f, sy = 0.f;

    int e = beg;
    for (; e + 32 <= end; e += 32) {
        unsigned int pk = g_edges[e + lane];
#pragma unroll 8
        for (int j = 0; j < 32; j++) {
            unsigned int p = __shfl_sync(0xffffffffu, pk, j);
            int   dj = (int)(p >> 14);
            float vj = (float)(p & 16383u) * VAL_INV;
            float2 xv = __half22float2(__ldg(&X[dj * 32 + lane]));
            sx = fmaf(vj, xv.x, sx);
            sy = fmaf(vj, xv.y, sy);
        }
    }
    int rem = end - e;
    if (rem > 0) {
        unsigned int pk = 0;
        if (lane < rem) pk = g_edges[e + lane];
        for (int j = 0; j < rem; j++) {
            unsigned int p = __shfl_sync(0xffffffffu, pk, j);
            int   dj = (int)(p >> 14);
            float vj = (float)(p & 16383u) * VAL_INV;
            float2 xv = __half22float2(__ldg(&X[dj * 32 + lane]));
            sx = fmaf(vj, xv.x, sx);
            sy = fmaf(vj, xv.y, sy);
        }
    }

    Xout[row * 32 + lane] = __floats2half2_rn(sx, sy);
}

// ---------------- final scores: one warp per pair --------------------------
// acc = x0(fp32 from inputs) + x1 + x2 + x3;  score = dot(acc_u, acc_i)/16
__global__ void k_score(const int* __restrict__ users,
                        const int* __restrict__ items,
                        const float2* __restrict__ user_emb,
                        const float2* __restrict__ item_emb,
                        float* __restrict__ out) {
    const int pair = (blockIdx.x * blockDim.x + threadIdx.x) >> 5;
    const int lane = threadIdx.x & 31;
    if (pair >= BATCH) return;

    int u  = users[pair];
    int it = items[pair];
    int urow = u;
    int irow = N_USERS + it;

    float2 au = user_emb[u * 32 + lane];
    float2 ai = item_emb[it * 32 + lane];
#pragma unroll
    for (int l = 1; l <= N_LAYERS; l++) {
        const __half2* __restrict__ X = (const __half2*)&g_xh[l][0];
        float2 xu = __half22float2(X[urow * 32 + lane]);
        float2 xi = __half22float2(X[irow * 32 + lane]);
        au.x += xu.x; au.y += xu.y;
        ai.x += xi.x; ai.y += xi.y;
    }

    float s = au.x * ai.x + au.y * ai.y;
#pragma unroll
    for (int off = 16; off > 0; off >>= 1)
        s += __shfl_xor_sync(0xffffffffu, s, off);
    if (lane == 0) out[pair] = s * (1.0f / 16.0f);
}

// ---------------- launch ----------------
extern "C" void kernel_launch(void* const* d_in, const int* in_sizes, int n_in,
                              void* d_out, int out_size) {
    const float* user_emb  = (const float*)d_in[0];
    const float* item_emb  = (const float*)d_in[1];
    const float* graph_val = (const float*)d_in[2];
    const int*   graph_src = (const int*)d_in[3];
    const int*   graph_dst = (const int*)d_in[4];
    const int*   users     = (const int*)d_in[5];
    const int*   items     = (const int*)d_in[6];
    float* out = (float*)d_out;

    // CSR build
    k_zero_counts<<<(NNODES + 1 + 255) / 256, 256>>>();
    k_hist<<<(NNZ / 4 + 255) / 256, 256>>>((const int4*)graph_src);
    k_scan1<<<NPART, 1024>>>();
    k_scan2<<<1, 256>>>();
    k_scan3<<<NPART - 1, 1024>>>();
    k_scatter<<<(NNZ / 4 + 255) / 256, 256>>>((const int4*)graph_src,
                                              (const int4*)graph_dst,
                                              (const float4*)graph_val);

    // x0 -> fp16
    k_init_x<<<(NNODES * EMB_DIM / 2 + 255) / 256, 256>>>(
        (const float2*)user_emb, (const float2*)item_emb);

    // 3 propagation layers (warp per row, 8 warps/block)
    const int spmm_blocks = (NNODES + 7) / 8;
    for (int l = 1; l <= N_LAYERS; l++)
        k_spmm<<<spmm_blocks, 256>>>(l);

    // scores
    k_score<<<(BATCH + 7) / 8, 256>>>(users, items,
                                      (const float2*)user_emb,
                                      (const float2*)item_emb, out);
}

// round 4
// speedup vs baseline: 1.4050x; 1.2232x over previous
#include <cuda_runtime.h>
#include <cuda_fp16.h>
#include <stdint.h>

// ---------------- problem constants ----------------
#define N_USERS 100000
#define N_ITEMS 50000
#define NNODES  150000           // N_USERS + N_ITEMS
#define EMB_DIM 64
#define NNZ     6400000
#define BATCH   4096
#define N_LAYERS 3

#define HIST_T  (NNZ / 4)                 // int4 hist work items
#define INIT_T  (NNODES * EMB_DIM / 4)    // float4 init work items
#define SCAN_BLOCKS ((NNODES + 1 + 1023) / 1024)   // 147 (<= #SMs, all resident)

// ---------------- device scratch (static, allocation-free) ----------------
// NOTE: relies on zero-initialization of __device__ globals for the FIRST call;
// k_cleanup re-zeroes g_rowptr / g_scan_pkt at the end of EVERY call so each
// call performs identical work (deterministic, graph-capture safe).
__device__ int                         g_rowptr[NNODES + 1];
__device__ volatile unsigned long long g_scan_pkt[SCAN_BLOCKS]; // (flag<<32)|value
__device__ unsigned short              g_rank[NNZ];
__device__ int2                        g_edges[NNZ];            // {dst, val fp32 bits}
__device__ __half                      g_xh[N_LAYERS + 1][NNODES * EMB_DIM];

// ---------------- fused histogram (+rank) and x0 fp16 init -----------------
__global__ void k_hist_init(const int4* __restrict__ src4,
                            const float4* __restrict__ user_emb,
                            const float4* __restrict__ item_emb) {
    int t = blockIdx.x * blockDim.x + threadIdx.x;
    if (t < HIST_T) {
        int4 s = src4[t];
        ushort4 r;
        r.x = (unsigned short)atomicAdd(&g_rowptr[s.x + 1], 1);
        r.y = (unsigned short)atomicAdd(&g_rowptr[s.y + 1], 1);
        r.z = (unsigned short)atomicAdd(&g_rowptr[s.z + 1], 1);
        r.w = (unsigned short)atomicAdd(&g_rowptr[s.w + 1], 1);
        ((ushort4*)g_rank)[t] = r;
    } else {
        int i = t - HIST_T;
        if (i < INIT_T) {
            const int us = N_USERS * EMB_DIM / 4;
            float4 v = (i < us) ? user_emb[i] : item_emb[i - us];
            __half2 a = __floats2half2_rn(v.x, v.y);
            __half2 b = __floats2half2_rn(v.z, v.w);
            uint2 o;
            o.x = *reinterpret_cast<unsigned int*>(&a);
            o.y = *reinterpret_cast<unsigned int*>(&b);
            ((uint2*)&g_xh[0][0])[i] = o;
        }
    }
}

// ---------------- single-pass decoupled-lookback inclusive scan ------------
__global__ void __launch_bounds__(1024) k_scan() {
    __shared__ int warp_sums[32];
    __shared__ int s_prefix;
    const int lane = threadIdx.x & 31;
    const int wid  = threadIdx.x >> 5;
    const int b    = blockIdx.x;
    int idx = b * 1024 + (int)threadIdx.x;
    int v = (idx <= NNODES) ? g_rowptr[idx] : 0;

    // block-local inclusive scan
    int x = v;
#pragma unroll
    for (int off = 1; off < 32; off <<= 1) {
        int t = __shfl_up_sync(0xffffffffu, x, off);
        if (lane >= off) x += t;
    }
    if (lane == 31) warp_sums[wid] = x;
    __syncthreads();
    if (wid == 0) {
        int w = warp_sums[lane];
#pragma unroll
        for (int off = 1; off < 32; off <<= 1) {
            int t = __shfl_up_sync(0xffffffffu, w, off);
            if (lane >= off) w += t;
        }
        warp_sums[lane] = w;
    }
    __syncthreads();
    int incl = x + ((wid > 0) ? warp_sums[wid - 1] : 0);
    int block_total = warp_sums[31];

    // decoupled lookback (thread 0); flag/value packed in one 64-bit word
    if (threadIdx.x == 0) {
        if (b == 0) {
            g_scan_pkt[0] = (2ull << 32) | (unsigned int)block_total;
            s_prefix = 0;
        } else {
            g_scan_pkt[b] = (1ull << 32) | (unsigned int)block_total;
            int prefix = 0;
            int p = b - 1;
            while (true) {
                unsigned long long q;
                do { q = g_scan_pkt[p]; } while ((q >> 32) == 0ull);
                prefix += (int)(unsigned int)q;
                if ((q >> 32) == 2ull) break;
                p--;
            }
            g_scan_pkt[b] = (2ull << 32) | (unsigned int)(prefix + block_total);
            s_prefix = prefix;
        }
    }
    __syncthreads();
    if (idx <= NNODES) g_rowptr[idx] = incl + s_prefix;
}

// ---------------- atomic-free scatter: pos = rowptr[src] + rank ------------
__global__ void k_scatter(const int4* __restrict__ src4,
                          const int4* __restrict__ dst4,
                          const float4* __restrict__ val4) {
    int t = blockIdx.x * blockDim.x + threadIdx.x;
    if (t < NNZ / 4) {
        int4    s = src4[t];
        int4    d = dst4[t];
        float4  v = val4[t];
        ushort4 r = ((const ushort4*)g_rank)[t];
        int p0 = g_rowptr[s.x] + r.x;
        int p1 = g_rowptr[s.y] + r.y;
        int p2 = g_rowptr[s.z] + r.z;
        int p3 = g_rowptr[s.w] + r.w;
        g_edges[p0] = make_int2(d.x, __float_as_int(v.x));
        g_edges[p1] = make_int2(d.y, __float_as_int(v.y));
        g_edges[p2] = make_int2(d.z, __float_as_int(v.z));
        g_edges[p3] = make_int2(d.w, __float_as_int(v.w));
    }
}

// ---------------- SpMM: warp per row, pull CSR, fp16 features --------------
__global__ void __launch_bounds__(256) k_spmm(int layer) {
    const int row  = (blockIdx.x * blockDim.x + threadIdx.x) >> 5;
    const int lane = threadIdx.x & 31;
    if (row >= NNODES) return;

    const __half2* __restrict__ X = (const __half2*)&g_xh[layer - 1][0];
    __half2* __restrict__ Xout    = (__half2*)&g_xh[layer][0];

    int beg = g_rowptr[row];
    int end = g_rowptr[row + 1];

    float sx = 0.f, sy = 0.f;

    int e = beg;
    for (; e + 32 <= end; e += 32) {
        int2 ev = g_edges[e + lane];
#pragma unroll
        for (int j = 0; j < 32; j++) {
            int   dj = __shfl_sync(0xffffffffu, ev.x, j);
            float vj = __int_as_float(__shfl_sync(0xffffffffu, ev.y, j));
            float2 xv = __half22float2(__ldg(&X[dj * 32 + lane]));
            sx = fmaf(vj, xv.x, sx);
            sy = fmaf(vj, xv.y, sy);
        }
    }
    int rem = end - e;
    if (rem > 0) {
        int2 ev = make_int2(0, 0);
        if (lane < rem) ev = g_edges[e + lane];
        for (int j = 0; j < rem; j++) {
            int   dj = __shfl_sync(0xffffffffu, ev.x, j);
            float vj = __int_as_float(__shfl_sync(0xffffffffu, ev.y, j));
            float2 xv = __half22float2(__ldg(&X[dj * 32 + lane]));
            sx = fmaf(vj, xv.x, sx);
            sy = fmaf(vj, xv.y, sy);
        }
    }

    Xout[row * 32 + lane] = __floats2half2_rn(sx, sy);
}

// ---------------- final scores: one warp per pair --------------------------
__global__ void k_score(const int* __restrict__ users,
                        const int* __restrict__ items,
                        const float2* __restrict__ user_emb,
                        const float2* __restrict__ item_emb,
                        float* __restrict__ out) {
    const int pair = (blockIdx.x * blockDim.x + threadIdx.x) >> 5;
    const int lane = threadIdx.x & 31;
    if (pair >= BATCH) return;

    int u  = users[pair];
    int it = items[pair];
    int urow = u;
    int irow = N_USERS + it;

    float2 au = user_emb[u * 32 + lane];
    float2 ai = item_emb[it * 32 + lane];
#pragma unroll
    for (int l = 1; l <= N_LAYERS; l++) {
        const __half2* __restrict__ X = (const __half2*)&g_xh[l][0];
        float2 xu = __half22float2(X[urow * 32 + lane]);
        float2 xi = __half22float2(X[irow * 32 + lane]);
        au.x += xu.x; au.y += xu.y;
        ai.x += xi.x; ai.y += xi.y;
    }

    float s = au.x * ai.x + au.y * ai.y;
#pragma unroll
    for (int off = 16; off > 0; off >>= 1)
        s += __shfl_xor_sync(0xffffffffu, s, off);
    if (lane == 0) out[pair] = s * (1.0f / 16.0f);
}

// ---------------- cleanup: restore zeroed state for next call --------------
__global__ void k_cleanup() {
    int i = blockIdx.x * blockDim.x + threadIdx.x;
    if (i <= NNODES) g_rowptr[i] = 0;
    if (i < SCAN_BLOCKS) g_scan_pkt[i] = 0ull;
}

// ---------------- launch ----------------
extern "C" void kernel_launch(void* const* d_in, const int* in_sizes, int n_in,
                              void* d_out, int out_size) {
    const float* user_emb  = (const float*)d_in[0];
    const float* item_emb  = (const float*)d_in[1];
    const float* graph_val = (const float*)d_in[2];
    const int*   graph_src = (const int*)d_in[3];
    const int*   graph_dst = (const int*)d_in[4];
    const int*   users     = (const int*)d_in[5];
    const int*   items     = (const int*)d_in[6];
    float* out = (float*)d_out;

    // launch 0: fused histogram(+ranks) and x0->fp16 init
    k_hist_init<<<(HIST_T + INIT_T + 255) / 256, 256>>>(
        (const int4*)graph_src, (const float4*)user_emb, (const float4*)item_emb);

    // launch 1: single-pass scan (decoupled lookback)
    k_scan<<<SCAN_BLOCKS, 1024>>>();

    // launch 2: scatter into CSR order
    k_scatter<<<(NNZ / 4 + 255) / 256, 256>>>((const int4*)graph_src,
                                              (const int4*)graph_dst,
                                              (const float4*)graph_val);

    // launches 3-5: propagation layers (warp per row)  [launch 3 = ncu window]
    const int spmm_blocks = (NNODES + 7) / 8;
    for (int l = 1; l <= N_LAYERS; l++)
        k_spmm<<<spmm_blocks, 256>>>(l);

    // launch 6: scores
    k_score<<<(BATCH + 7) / 8, 256>>>(users, items,
                                      (const float2*)user_emb,
                                      (const float2*)item_emb, out);

    // launch 7: re-zero counters/flags for the next call
    k_cleanup<<<(NNODES + 1 + 255) / 256, 256>>>();
}

// round 5
// speedup vs baseline: 1.5608x; 1.1108x over previous
#include <cuda_runtime.h>
#include <cuda_fp16.h>
#include <stdint.h>

// ---------------- problem constants ----------------
#define N_USERS 100000
#define N_ITEMS 50000
#define NNODES  150000           // N_USERS + N_ITEMS
#define EMB_DIM 64
#define NNZ     6400000
#define BATCH   4096
#define N_LAYERS 3

#define HIST_T  (NNZ / 4)                 // int4 hist work items
#define INIT_T  (NNODES * EMB_DIM / 4)    // float4 init work items
#define SCAN_BLOCKS ((NNODES + 1 + 1023) / 1024)   // 147 (<= #SMs, all resident)

// ---------------- device scratch (static, allocation-free) ----------------
// Zero-init covers the FIRST call; k_cleanup re-zeroes g_rowptr / g_scan_pkt
// at the end of EVERY call so each call performs identical work.
__device__ int                         g_rowptr[NNODES + 1];
__device__ volatile unsigned long long g_scan_pkt[SCAN_BLOCKS]; // (flag<<32)|value
__device__ unsigned short              g_rank[NNZ];
__device__ int2                        g_edges[NNZ];            // {dst, val fp32 bits}
__device__ __half                      g_xh[N_LAYERS + 1][NNODES * EMB_DIM];

// ---------------- fused histogram (+rank) and x0 fp16 init -----------------
__global__ void k_hist_init(const int4* __restrict__ src4,
                            const float4* __restrict__ user_emb,
                            const float4* __restrict__ item_emb) {
    int t = blockIdx.x * blockDim.x + threadIdx.x;
    if (t < HIST_T) {
        int4 s = src4[t];
        ushort4 r;
        r.x = (unsigned short)atomicAdd(&g_rowptr[s.x + 1], 1);
        r.y = (unsigned short)atomicAdd(&g_rowptr[s.y + 1], 1);
        r.z = (unsigned short)atomicAdd(&g_rowptr[s.z + 1], 1);
        r.w = (unsigned short)atomicAdd(&g_rowptr[s.w + 1], 1);
        ((ushort4*)g_rank)[t] = r;
    } else {
        int i = t - HIST_T;
        if (i < INIT_T) {
            const int us = N_USERS * EMB_DIM / 4;
            float4 v = (i < us) ? user_emb[i] : item_emb[i - us];
            __half2 a = __floats2half2_rn(v.x, v.y);
            __half2 b = __floats2half2_rn(v.z, v.w);
            uint2 o;
            o.x = *reinterpret_cast<unsigned int*>(&a);
            o.y = *reinterpret_cast<unsigned int*>(&b);
            ((uint2*)&g_xh[0][0])[i] = o;
        }
    }
}

// ---------------- single-pass decoupled-lookback inclusive scan ------------
__global__ void __launch_bounds__(1024) k_scan() {
    __shared__ int warp_sums[32];
    __shared__ int s_prefix;
    const int lane = threadIdx.x & 31;
    const int wid  = threadIdx.x >> 5;
    const int b    = blockIdx.x;
    int idx = b * 1024 + (int)threadIdx.x;
    int v = (idx <= NNODES) ? g_rowptr[idx] : 0;

    int x = v;
#pragma unroll
    for (int off = 1; off < 32; off <<= 1) {
        int t = __shfl_up_sync(0xffffffffu, x, off);
        if (lane >= off) x += t;
    }
    if (lane == 31) warp_sums[wid] = x;
    __syncthreads();
    if (wid == 0) {
        int w = warp_sums[lane];
#pragma unroll
        for (int off = 1; off < 32; off <<= 1) {
            int t = __shfl_up_sync(0xffffffffu, w, off);
            if (lane >= off) w += t;
        }
        warp_sums[lane] = w;
    }
    __syncthreads();
    int incl = x + ((wid > 0) ? warp_sums[wid - 1] : 0);
    int block_total = warp_sums[31];

    if (threadIdx.x == 0) {
        if (b == 0) {
            g_scan_pkt[0] = (2ull << 32) | (unsigned int)block_total;
            s_prefix = 0;
        } else {
            g_scan_pkt[b] = (1ull << 32) | (unsigned int)block_total;
            int prefix = 0;
            int p = b - 1;
            while (true) {
                unsigned long long q;
                do { q = g_scan_pkt[p]; } while ((q >> 32) == 0ull);
                prefix += (int)(unsigned int)q;
                if ((q >> 32) == 2ull) break;
                p--;
            }
            g_scan_pkt[b] = (2ull << 32) | (unsigned int)(prefix + block_total);
            s_prefix = prefix;
        }
    }
    __syncthreads();
    if (idx <= NNODES) g_rowptr[idx] = incl + s_prefix;
}

// ---------------- atomic-free scatter: pos = rowptr[src] + rank ------------
__global__ void k_scatter(const int4* __restrict__ src4,
                          const int4* __restrict__ dst4,
                          const float4* __restrict__ val4) {
    int t = blockIdx.x * blockDim.x + threadIdx.x;
    if (t < NNZ / 4) {
        int4    s = src4[t];
        int4    d = dst4[t];
        float4  v = val4[t];
        ushort4 r = ((const ushort4*)g_rank)[t];
        int p0 = g_rowptr[s.x] + r.x;
        int p1 = g_rowptr[s.y] + r.y;
        int p2 = g_rowptr[s.z] + r.z;
        int p3 = g_rowptr[s.w] + r.w;
        g_edges[p0] = make_int2(d.x, __float_as_int(v.x));
        g_edges[p1] = make_int2(d.y, __float_as_int(v.y));
        g_edges[p2] = make_int2(d.z, __float_as_int(v.z));
        g_edges[p3] = make_int2(d.w, __float_as_int(v.w));
    }
}

// ---------------- SpMM: warp per row, 4 edges/step, uint4 gathers ----------
// Lane groups of 8: group g = lane>>3 handles edge (step*4+g); lane loads the
// uint4 (8 halves) at column block (lane&7). fp32 accumulation throughout.
__global__ void __launch_bounds__(256) k_spmm(int layer) {
    const int row  = (blockIdx.x * blockDim.x + threadIdx.x) >> 5;
    const int lane = threadIdx.x & 31;
    if (row >= NNODES) return;

    const uint4* __restrict__ Xv = (const uint4*)&g_xh[layer - 1][0]; // 8 uint4/row
    uint4* __restrict__ Xout     = (uint4*)&g_xh[layer][0];

    const int col = lane & 7;
    const int grp = lane >> 3;

    int beg = g_rowptr[row];
    int end = g_rowptr[row + 1];

    float a0 = 0.f, a1 = 0.f, a2 = 0.f, a3 = 0.f;
    float a4 = 0.f, a5 = 0.f, a6 = 0.f, a7 = 0.f;

    int e = beg;
    for (; e + 32 <= end; e += 32) {
        int2 ev = g_edges[e + lane];
#pragma unroll
        for (int s = 0; s < 8; s++) {
            int jidx = s * 4 + grp;
            int   dj = __shfl_sync(0xffffffffu, ev.x, jidx);
            float vj = __int_as_float(__shfl_sync(0xffffffffu, ev.y, jidx));
            uint4 q = __ldg(&Xv[dj * 8 + col]);
            __half2 h0 = *reinterpret_cast<__half2*>(&q.x);
            __half2 h1 = *reinterpret_cast<__half2*>(&q.y);
            __half2 h2 = *reinterpret_cast<__half2*>(&q.z);
            __half2 h3 = *reinterpret_cast<__half2*>(&q.w);
            a0 = fmaf(vj, __low2float(h0),  a0);
            a1 = fmaf(vj, __high2float(h0), a1);
            a2 = fmaf(vj, __low2float(h1),  a2);
            a3 = fmaf(vj, __high2float(h1), a3);
            a4 = fmaf(vj, __low2float(h2),  a4);
            a5 = fmaf(vj, __high2float(h2), a5);
            a6 = fmaf(vj, __low2float(h3),  a6);
            a7 = fmaf(vj, __high2float(h3), a7);
        }
    }
    int rem = end - e;
    if (rem > 0) {
        int2 ev = (lane < rem) ? g_edges[e + lane] : make_int2(0, 0);
        int nsteps = (rem + 3) >> 2;
        for (int s = 0; s < nsteps; s++) {
            int jidx = s * 4 + grp;
            int   dj = __shfl_sync(0xffffffffu, ev.x, jidx);
            int   vb = __shfl_sync(0xffffffffu, ev.y, jidx);
            if (jidx >= rem) { dj = 0; vb = 0; }
            float vj = __int_as_float(vb);
            uint4 q = __ldg(&Xv[dj * 8 + col]);
            __half2 h0 = *reinterpret_cast<__half2*>(&q.x);
            __half2 h1 = *reinterpret_cast<__half2*>(&q.y);
            __half2 h2 = *reinterpret_cast<__half2*>(&q.z);
            __half2 h3 = *reinterpret_cast<__half2*>(&q.w);
            a0 = fmaf(vj, __low2float(h0),  a0);
            a1 = fmaf(vj, __high2float(h0), a1);
            a2 = fmaf(vj, __low2float(h1),  a2);
            a3 = fmaf(vj, __high2float(h1), a3);
            a4 = fmaf(vj, __low2float(h2),  a4);
            a5 = fmaf(vj, __high2float(h2), a5);
            a6 = fmaf(vj, __low2float(h3),  a6);
            a7 = fmaf(vj, __high2float(h3), a7);
        }
    }

    // reduce the 4 lane-groups (xor 8, then xor 16)
#pragma unroll
    for (int off = 8; off <= 16; off <<= 1) {
        a0 += __shfl_xor_sync(0xffffffffu, a0, off);
        a1 += __shfl_xor_sync(0xffffffffu, a1, off);
        a2 += __shfl_xor_sync(0xffffffffu, a2, off);
        a3 += __shfl_xor_sync(0xffffffffu, a3, off);
        a4 += __shfl_xor_sync(0xffffffffu, a4, off);
        a5 += __shfl_xor_sync(0xffffffffu, a5, off);
        a6 += __shfl_xor_sync(0xffffffffu, a6, off);
        a7 += __shfl_xor_sync(0xffffffffu, a7, off);
    }

    if (lane < 8) {
        __half2 o0 = __floats2half2_rn(a0, a1);
        __half2 o1 = __floats2half2_rn(a2, a3);
        __half2 o2 = __floats2half2_rn(a4, a5);
        __half2 o3 = __floats2half2_rn(a6, a7);
        uint4 o;
        o.x = *reinterpret_cast<unsigned int*>(&o0);
        o.y = *reinterpret_cast<unsigned int*>(&o1);
        o.z = *reinterpret_cast<unsigned int*>(&o2);
        o.w = *reinterpret_cast<unsigned int*>(&o3);
        Xout[row * 8 + lane] = o;
    }
}

// ---------------- final scores: one warp per pair --------------------------
__global__ void k_score(const int* __restrict__ users,
                        const int* __restrict__ items,
                        const float2* __restrict__ user_emb,
                        const float2* __restrict__ item_emb,
                        float* __restrict__ out) {
    const int pair = (blockIdx.x * blockDim.x + threadIdx.x) >> 5;
    const int lane = threadIdx.x & 31;
    if (pair >= BATCH) return;

    int u  = users[pair];
    int it = items[pair];
    int urow = u;
    int irow = N_USERS + it;

    float2 au = user_emb[u * 32 + lane];
    float2 ai = item_emb[it * 32 + lane];
#pragma unroll
    for (int l = 1; l <= N_LAYERS; l++) {
        const __half2* __restrict__ X = (const __half2*)&g_xh[l][0];
        float2 xu = __half22float2(X[urow * 32 + lane]);
        float2 xi = __half22float2(X[irow * 32 + lane]);
        au.x += xu.x; au.y += xu.y;
        ai.x += xi.x; ai.y += xi.y;
    }

    float s = au.x * ai.x + au.y * ai.y;
#pragma unroll
    for (int off = 16; off > 0; off >>= 1)
        s += __shfl_xor_sync(0xffffffffu, s, off);
    if (lane == 0) out[pair] = s * (1.0f / 16.0f);
}

// ---------------- cleanup: restore zeroed state for next call --------------
__global__ void k_cleanup() {
    int i = blockIdx.x * blockDim.x + threadIdx.x;
    if (i <= NNODES) g_rowptr[i] = 0;
    if (i < SCAN_BLOCKS) g_scan_pkt[i] = 0ull;
}

// ---------------- launch ----------------
extern "C" void kernel_launch(void* const* d_in, const int* in_sizes, int n_in,
                              void* d_out, int out_size) {
    const float* user_emb  = (const float*)d_in[0];
    const float* item_emb  = (const float*)d_in[1];
    const float* graph_val = (const float*)d_in[2];
    const int*   graph_src = (const int*)d_in[3];
    const int*   graph_dst = (const int*)d_in[4];
    const int*   users     = (const int*)d_in[5];
    const int*   items     = (const int*)d_in[6];
    float* out = (float*)d_out;

    // launch 0: fused histogram(+ranks) and x0->fp16 init
    k_hist_init<<<(HIST_T + INIT_T + 255) / 256, 256>>>(
        (const int4*)graph_src, (const float4*)user_emb, (const float4*)item_emb);

    // launch 1: single-pass scan (decoupled lookback)
    k_scan<<<SCAN_BLOCKS, 1024>>>();

    // launch 2: scatter into CSR order
    k_scatter<<<(NNZ / 4 + 255) / 256, 256>>>((const int4*)graph_src,
                                              (const int4*)graph_dst,
                                              (const float4*)graph_val);

    // launches 3-5: propagation layers (warp per row)  [launch 3 = ncu window]
    const int spmm_blocks = (NNODES + 7) / 8;
    for (int l = 1; l <= N_LAYERS; l++)
        k_spmm<<<spmm_blocks, 256>>>(l);

    // launch 6: scores
    k_score<<<(BATCH + 7) / 8, 256>>>(users, items,
                                      (const float2*)user_emb,
                                      (const float2*)item_emb, out);

    // launch 7: re-zero counters/flags for the next call
    k_cleanup<<<(NNODES + 1 + 255) / 256, 256>>>();
}